// round 10
// baseline (speedup 1.0000x reference)
#include <cuda_runtime.h>
#include <cuda_bf16.h>

// STFT: B=16, T=262144, n_fft=2048, hop=512, center reflect pad 1024.
// n_frames = 513, n_bins = 1025. Output [real(16,1025,513); imag(...)] fp32.
//
// 4 frames/CTA (256 thr, 64 thr/frame). 1024-pt complex FFT (real packing),
// Stockham radices 8,8,4,4; stage 1 reads gmem; stage 4 fused with rfft
// unpack; X written once to smem; transposed store (16B runs).
// __launch_bounds__(256,5): 51 regs -> 5 CTAs/SM, 40 warps (62.5% occ).

#define NC        1024
#define SROW      1026      // float2 row stride: 2*SROW == 4 (mod 32) banks
#define HOP       512
#define PADC      1024
#define T_LEN     262144
#define NFFT      2048
#define NFRAMES   513
#define NBINS     1025
#define NB        16
#define THREADS   256
#define FPB       4
#define NGRP      129
#define PI_F      3.14159265358979323846f
#define C4        0.70710678118654752f

#define PHY(i) ((i) ^ ((((unsigned)(i)) >> 3) & 15u))

__device__ __forceinline__ float2 cadd(float2 a, float2 b) { return make_float2(a.x + b.x, a.y + b.y); }
__device__ __forceinline__ float2 csub(float2 a, float2 b) { return make_float2(a.x - b.x, a.y - b.y); }
__device__ __forceinline__ float2 cmulc(float2 a, float2 w) {
    return make_float2(a.x * w.x - a.y * w.y, a.x * w.y + a.y * w.x);
}

__device__ __forceinline__ void fft8(float2* a) {
    float2 e0 = cadd(a[0], a[4]), e1 = cadd(a[1], a[5]);
    float2 e2 = cadd(a[2], a[6]), e3 = cadd(a[3], a[7]);
    float2 o0 = csub(a[0], a[4]), o1 = csub(a[1], a[5]);
    float2 o2 = csub(a[2], a[6]), o3 = csub(a[3], a[7]);
    float2 ee0 = cadd(e0, e2), ee1 = cadd(e1, e3);
    float2 eo0 = csub(e0, e2), eo1 = csub(e1, e3);
    a[0] = cadd(ee0, ee1);
    a[4] = csub(ee0, ee1);
    a[2] = make_float2(eo0.x + eo1.y, eo0.y - eo1.x);
    a[6] = make_float2(eo0.x - eo1.y, eo0.y + eo1.x);
    float2 p1 = make_float2(C4 * (o1.x + o1.y), C4 * (o1.y - o1.x));
    float2 p2 = make_float2(o2.y, -o2.x);
    float2 p3 = make_float2(C4 * (o3.y - o3.x), -C4 * (o3.x + o3.y));
    float2 s0 = cadd(o0, p2), s1 = cadd(p1, p3);
    float2 d0 = csub(o0, p2), d1 = csub(p1, p3);
    a[1] = cadd(s0, s1);
    a[5] = csub(s0, s1);
    a[3] = make_float2(d0.x + d1.y, d0.y - d1.x);
    a[7] = make_float2(d0.x - d1.y, d0.y + d1.x);
}

__device__ __forceinline__ void fft4(float2& a0, float2& a1, float2& a2, float2& a3) {
    float2 t0 = cadd(a0, a2), t1 = csub(a0, a2);
    float2 t2 = cadd(a1, a3), t3 = csub(a1, a3);
    a0 = cadd(t0, t2);
    a2 = csub(t0, t2);
    float2 b1 = make_float2(t1.x + t3.y, t1.y - t3.x);
    float2 b3 = make_float2(t1.x - t3.y, t1.y + t3.x);
    a1 = b1;
    a3 = b3;
}

// apply w^r to a[1..7] with a serial chain (minimal live registers)
__device__ __forceinline__ void twiddle8(float2* a, float2 w1) {
    float2 wk = w1;
    a[1] = cmulc(a[1], wk);
#pragma unroll
    for (int r = 2; r < 8; r++) { wk = cmulc(wk, w1); a[r] = cmulc(a[r], wk); }
}

__device__ __forceinline__ void bar_frame(int fl) {
    asm volatile("bar.sync %0, 64;" :: "r"(fl + 1) : "memory");
}

__device__ __forceinline__ void unpack_pair(float2 zk, float2 zn, float cw, float sw,
                                            float2& Xk, float2& Xc) {
    const float er  = 0.5f * (zk.x + zn.x);
    const float ei  = 0.5f * (zk.y - zn.y);
    const float orr = 0.5f * (zk.y + zn.y);
    const float oi  = 0.5f * (zn.x - zk.x);
    const float pr  = orr * cw + oi * sw;
    const float pi2 = orr * sw - oi * cw;
    Xk = make_float2(er + pr,  ei - pi2);
    Xc = make_float2(er - pr, -ei - pi2);
}

__global__ __launch_bounds__(THREADS, 5)
void stft_kernel(const float* __restrict__ x,
                 const float* __restrict__ win,
                 float* __restrict__ out) {
    __shared__ float2 buf[FPB * SROW];   // 32,832 B

    const int g   = blockIdx.x % NGRP;
    const int b   = blockIdx.x / NGRP;
    const int tid = threadIdx.x;
    const int fl  = tid >> 6;          // frame slot 0..3
    const int u   = tid & 63;          // lane within frame
    const int f   = g * FPB + fl;      // phantom if >= 513
    const float* __restrict__ xb = x + (long)b * T_LEN;
    const int base = f * HOP - PADC;
    float2* __restrict__ row = buf + fl * SROW;

    // ---- stage 1: radix-8, n=1024, s=1 — read gmem directly ----
    const bool interior = (base >= 0) && (base + NFFT <= T_LEN);
#pragma unroll
    for (int h = 0; h < 2; h++) {
        const int t = u + (h << 6);
        float s1, c1;
        __sincosf((float)t * (-2.0f * PI_F / 1024.0f), &s1, &c1);
        float2 a[8];
        if (interior) {
            const float2* __restrict__ xv = (const float2*)(xb + base);
            const float2* __restrict__ wv = (const float2*)win;
#pragma unroll
            for (int r = 0; r < 8; r++) {
                const int n = t + (r << 7);
                const float2 v = xv[n];
                const float2 w = wv[n];
                a[r] = make_float2(v.x * w.x, v.y * w.y);
            }
        } else {
#pragma unroll
            for (int r = 0; r < 8; r++) {
                const int n = t + (r << 7);
                int t0 = base + 2 * n;
                int t1 = base + 2 * n + 1;
                t0 = (t0 < 0) ? -t0 : ((t0 >= T_LEN) ? 2 * T_LEN - 2 - t0 : t0);
                t1 = (t1 < 0) ? -t1 : ((t1 >= T_LEN) ? 2 * T_LEN - 2 - t1 : t1);
                a[r] = make_float2(xb[t0] * win[2 * n], xb[t1] * win[2 * n + 1]);
            }
        }
        fft8(a);
        twiddle8(a, make_float2(c1, s1));
#pragma unroll
        for (int r = 0; r < 8; r++) row[PHY(8 * t + r)] = a[r];
    }
    bar_frame(fl);

    // ---- stage 2: radix-8, n=128, s=8 ----
    {
        float2 A[2][8];
#pragma unroll
        for (int h = 0; h < 2; h++) {
            const int t = u + (h << 6);
#pragma unroll
            for (int r = 0; r < 8; r++) A[h][r] = row[PHY(t + (r << 7))];
        }
        bar_frame(fl);
#pragma unroll
        for (int h = 0; h < 2; h++) {
            const int t = u + (h << 6);
            fft8(A[h]);
            const int p = t >> 3;
            float s1, c1;
            __sincosf((float)p * (-2.0f * PI_F / 128.0f), &s1, &c1);
            twiddle8(A[h], make_float2(c1, s1));
            const int dbase = t + 56 * p;
#pragma unroll
            for (int r = 0; r < 8; r++) row[PHY(dbase + 8 * r)] = A[h][r];
        }
        bar_frame(fl);
    }

    // ---- stage 3: radix-4 x4, n=16, s=64 ----
    {
        float2 A4[4][4];
#pragma unroll
        for (int h = 0; h < 4; h++) {
            const int t = u + (h << 6);
#pragma unroll
            for (int r = 0; r < 4; r++) A4[h][r] = row[PHY(t + (r << 8))];
        }
        bar_frame(fl);
#pragma unroll
        for (int h = 0; h < 4; h++) {
            const int t = u + (h << 6);
            const int p = t >> 6;       // == h
            fft4(A4[h][0], A4[h][1], A4[h][2], A4[h][3]);
            float s1, c1;
            __sincosf((float)p * (-2.0f * PI_F / 16.0f), &s1, &c1);
            const float2 w1 = make_float2(c1, s1);
            const float2 w2 = cmulc(w1, w1);
            const float2 w3 = cmulc(w1, w2);
            const int dbase = t + 192 * p;
            row[PHY(dbase)]       = A4[h][0];
            row[PHY(dbase + 64)]  = cmulc(A4[h][1], w1);
            row[PHY(dbase + 128)] = cmulc(A4[h][2], w2);
            row[PHY(dbase + 192)] = cmulc(A4[h][3], w3);
        }
        bar_frame(fl);
    }

    // ---- stage 4 (radix-4, trivial twiddles) fused with rfft unpack ----
    {
        float ca, sa;
        __sincosf((float)u * (PI_F / 1024.0f), &sa, &ca);

        float2 Z1[2][4], Z2[2][4];
#pragma unroll
        for (int h = 0; h < 2; h++) {
            const int ue = u + (h << 6);
            const int t1 = ue;
            const int t2 = (ue == 0) ? 128 : 256 - ue;
#pragma unroll
            for (int r = 0; r < 4; r++) {
                Z1[h][r] = row[PHY(t1 + (r << 8))];
                Z2[h][r] = row[PHY(t2 + (r << 8))];
            }
        }
        bar_frame(fl);
#pragma unroll
        for (int h = 0; h < 2; h++) {
            const int ue = u + (h << 6);
            fft4(Z1[h][0], Z1[h][1], Z1[h][2], Z1[h][3]);
            fft4(Z2[h][0], Z2[h][1], Z2[h][2], Z2[h][3]);
            if (ue == 0) {
                row[0]    = make_float2(Z1[h][0].x + Z1[h][0].y, 0.0f);
                row[1024] = make_float2(Z1[h][0].x - Z1[h][0].y, 0.0f);
                row[512]  = make_float2(Z1[h][2].x, -Z1[h][2].y);
                float2 Xk, Xc;
                unpack_pair(Z1[h][1], Z1[h][3], C4, C4, Xk, Xc);
                row[256] = Xk; row[768] = Xc;
                unpack_pair(Z2[h][0], Z2[h][3], 0.92387953f, 0.38268343f, Xk, Xc);
                row[128] = Xk; row[896] = Xc;
                unpack_pair(Z2[h][1], Z2[h][2], 0.38268343f, 0.92387953f, Xk, Xc);
                row[384] = Xk; row[640] = Xc;
            } else {
                float cb, sb;
                if (h == 0) { cb = ca; sb = sa; }
                else {      // theta + pi/8 for ue = u + 64
                    cb = 0.98078528f * ca - 0.19509032f * sa;
                    sb = 0.98078528f * sa + 0.19509032f * ca;
                }
                const float cp = C4 * (cb - sb);
                const float sp = C4 * (cb + sb);
                float2 Xk, Xc;
                unpack_pair(Z1[h][0], Z2[h][3], cb, sb, Xk, Xc);
                row[ue] = Xk; row[1024 - ue] = Xc;
                unpack_pair(Z1[h][1], Z2[h][2], cp, sp, Xk, Xc);
                row[ue + 256] = Xk; row[768 - ue] = Xc;
                unpack_pair(Z1[h][2], Z2[h][1], -sb, cb, Xk, Xc);
                row[ue + 512] = Xk; row[512 - ue] = Xc;
                unpack_pair(Z1[h][3], Z2[h][0], -sp, cp, Xk, Xc);
                row[ue + 768] = Xk; row[256 - ue] = Xc;
            }
        }
    }
    __syncthreads();

    // ---- transposed store: lane j -> frame j&3, bin j>>2 (+64/iter) ----
    const int  fs     = tid & 3;
    const int  kb     = tid >> 2;         // 0..63
    const int  fstore = g * FPB + fs;
    const bool valid  = (fstore < NFRAMES);
    const long ro       = ((long)b * NBINS) * NFRAMES + fstore;
    const long imag_off = (long)NB * NBINS * NFRAMES;
    const float2* __restrict__ Xrow = buf + fs * SROW;
#pragma unroll
    for (int i = 0; i < 17; i++) {
        const int k = kb + (i << 6);
        if (k <= NC && valid) {
            const float2 X = Xrow[k];
            const long o = ro + (long)k * NFRAMES;
            out[o]            = X.x;
            out[imag_off + o] = X.y;
        }
    }
}

extern "C" void kernel_launch(void* const* d_in, const int* in_sizes, int n_in,
                              void* d_out, int out_size) {
    const float* x   = (const float*)d_in[0];
    const float* win = (const float*)d_in[1];
    float* out = (float*)d_out;
    stft_kernel<<<NB * NGRP, THREADS>>>(x, win, out);
}

// round 11
// speedup vs baseline: 1.0390x; 1.0390x over previous
#include <cuda_runtime.h>
#include <cuda_bf16.h>

// STFT: B=16, T=262144, n_fft=2048, hop=512, center reflect pad 1024.
// n_frames = 513, n_bins = 1025. Output [real(16,1025,513); imag(...)] fp32.
//
// 4 frames/CTA, 512 thr (128 thr/frame, ONE butterfly/thread/stage).
// Stockham radices 8,8,4,4 with PING-PONG smem buffers (A->B->A->X in B):
// no in-place hazard => only 8 float2 live per thread => <=42 regs =>
// 3 CTAs/SM (48 warps). Stage 1 reads gmem; stage 4 fused with rfft unpack.

#define NC        1024
#define SROW      1028      // float2 row stride: frames offset 8 bank-pairs
#define HOP       512
#define PADC      1024
#define T_LEN     262144
#define NFFT      2048
#define NFRAMES   513
#define NBINS     1025
#define NB        16
#define THREADS   512
#define FPB       4
#define NGRP      129
#define PI_F      3.14159265358979323846f
#define C4        0.70710678118654752f

#define PHY(i) ((i) ^ ((((unsigned)(i)) >> 3) & 15u))

__device__ __forceinline__ float2 cadd(float2 a, float2 b) { return make_float2(a.x + b.x, a.y + b.y); }
__device__ __forceinline__ float2 csub(float2 a, float2 b) { return make_float2(a.x - b.x, a.y - b.y); }
__device__ __forceinline__ float2 cmulc(float2 a, float2 w) {
    return make_float2(a.x * w.x - a.y * w.y, a.x * w.y + a.y * w.x);
}

__device__ __forceinline__ void fft8(float2* a) {
    float2 e0 = cadd(a[0], a[4]), e1 = cadd(a[1], a[5]);
    float2 e2 = cadd(a[2], a[6]), e3 = cadd(a[3], a[7]);
    float2 o0 = csub(a[0], a[4]), o1 = csub(a[1], a[5]);
    float2 o2 = csub(a[2], a[6]), o3 = csub(a[3], a[7]);
    float2 ee0 = cadd(e0, e2), ee1 = cadd(e1, e3);
    float2 eo0 = csub(e0, e2), eo1 = csub(e1, e3);
    a[0] = cadd(ee0, ee1);
    a[4] = csub(ee0, ee1);
    a[2] = make_float2(eo0.x + eo1.y, eo0.y - eo1.x);
    a[6] = make_float2(eo0.x - eo1.y, eo0.y + eo1.x);
    float2 p1 = make_float2(C4 * (o1.x + o1.y), C4 * (o1.y - o1.x));
    float2 p2 = make_float2(o2.y, -o2.x);
    float2 p3 = make_float2(C4 * (o3.y - o3.x), -C4 * (o3.x + o3.y));
    float2 s0 = cadd(o0, p2), s1 = cadd(p1, p3);
    float2 d0 = csub(o0, p2), d1 = csub(p1, p3);
    a[1] = cadd(s0, s1);
    a[5] = csub(s0, s1);
    a[3] = make_float2(d0.x + d1.y, d0.y - d1.x);
    a[7] = make_float2(d0.x - d1.y, d0.y + d1.x);
}

__device__ __forceinline__ void fft4(float2& a0, float2& a1, float2& a2, float2& a3) {
    float2 t0 = cadd(a0, a2), t1 = csub(a0, a2);
    float2 t2 = cadd(a1, a3), t3 = csub(a1, a3);
    a0 = cadd(t0, t2);
    a2 = csub(t0, t2);
    float2 b1 = make_float2(t1.x + t3.y, t1.y - t3.x);
    float2 b3 = make_float2(t1.x - t3.y, t1.y + t3.x);
    a1 = b1;
    a3 = b3;
}

// apply w^r to a[1..7] (serial chain: minimal live registers)
__device__ __forceinline__ void twiddle8(float2* a, float2 w1) {
    float2 wk = w1;
    a[1] = cmulc(a[1], wk);
#pragma unroll
    for (int r = 2; r < 8; r++) { wk = cmulc(wk, w1); a[r] = cmulc(a[r], wk); }
}

__device__ __forceinline__ void bar_frame(int fl) {
    asm volatile("bar.sync %0, 128;" :: "r"(fl + 1) : "memory");
}

__device__ __forceinline__ void unpack_pair(float2 zk, float2 zn, float cw, float sw,
                                            float2& Xk, float2& Xc) {
    const float er  = 0.5f * (zk.x + zn.x);
    const float ei  = 0.5f * (zk.y - zn.y);
    const float orr = 0.5f * (zk.y + zn.y);
    const float oi  = 0.5f * (zn.x - zk.x);
    const float pr  = orr * cw + oi * sw;
    const float pi2 = orr * sw - oi * cw;
    Xk = make_float2(er + pr,  ei - pi2);
    Xc = make_float2(er - pr, -ei - pi2);
}

extern __shared__ float2 smem[];   // 2 * FPB * SROW float2 = 65,792 B

__global__ __launch_bounds__(THREADS, 3)
void stft_kernel(const float* __restrict__ x,
                 const float* __restrict__ win,
                 float* __restrict__ out) {
    const int g   = blockIdx.x % NGRP;
    const int b   = blockIdx.x / NGRP;
    const int tid = threadIdx.x;
    const int fl  = tid >> 7;          // frame slot 0..3
    const int u   = tid & 127;         // lane within frame
    const int f   = g * FPB + fl;      // phantom if >= 513
    const float* __restrict__ xb = x + (long)b * T_LEN;
    const int base = f * HOP - PADC;
    float2* __restrict__ rowA = smem + fl * SROW;
    float2* __restrict__ rowB = smem + (FPB + fl) * SROW;

    // ---- stage 1: radix-8, n=1024, s=1 — gmem -> A. butterfly t = u ----
    {
        float s1, c1;
        __sincosf((float)u * (-2.0f * PI_F / 1024.0f), &s1, &c1);
        float2 a[8];
        const bool interior = (base >= 0) && (base + NFFT <= T_LEN);
        if (interior) {
            const float2* __restrict__ xv = (const float2*)(xb + base);
            const float2* __restrict__ wv = (const float2*)win;
#pragma unroll
            for (int r = 0; r < 8; r++) {
                const int n = u + (r << 7);
                const float2 v = xv[n];
                const float2 w = wv[n];
                a[r] = make_float2(v.x * w.x, v.y * w.y);
            }
        } else {
#pragma unroll
            for (int r = 0; r < 8; r++) {
                const int n = u + (r << 7);
                int t0 = base + 2 * n;
                int t1 = base + 2 * n + 1;
                t0 = (t0 < 0) ? -t0 : ((t0 >= T_LEN) ? 2 * T_LEN - 2 - t0 : t0);
                t1 = (t1 < 0) ? -t1 : ((t1 >= T_LEN) ? 2 * T_LEN - 2 - t1 : t1);
                a[r] = make_float2(xb[t0] * win[2 * n], xb[t1] * win[2 * n + 1]);
            }
        }
        fft8(a);
        twiddle8(a, make_float2(c1, s1));
#pragma unroll
        for (int r = 0; r < 8; r++) rowA[PHY(8 * u + r)] = a[r];
    }
    bar_frame(fl);

    // ---- stage 2: radix-8, n=128, s=8 — A -> B. butterfly t = u ----
    {
        const int p = u >> 3;
        float s1, c1;
        __sincosf((float)p * (-2.0f * PI_F / 128.0f), &s1, &c1);
        float2 a[8];
#pragma unroll
        for (int r = 0; r < 8; r++) a[r] = rowA[PHY(u + (r << 7))];
        fft8(a);
        twiddle8(a, make_float2(c1, s1));
        const int dbase = u + 56 * p;
#pragma unroll
        for (int r = 0; r < 8; r++) rowB[PHY(dbase + 8 * r)] = a[r];
    }
    bar_frame(fl);

    // ---- stage 3: radix-4, n=16, s=64 — B -> A. butterflies u, u+128 ----
#pragma unroll
    for (int h = 0; h < 2; h++) {
        const int t = u + (h << 7);
        const int p = t >> 6;
        float2 a0 = rowB[PHY(t)];
        float2 a1 = rowB[PHY(t + 256)];
        float2 a2 = rowB[PHY(t + 512)];
        float2 a3 = rowB[PHY(t + 768)];
        fft4(a0, a1, a2, a3);
        float s1, c1;
        __sincosf((float)p * (-2.0f * PI_F / 16.0f), &s1, &c1);
        const float2 w1 = make_float2(c1, s1);
        const float2 w2 = cmulc(w1, w1);
        const float2 w3 = cmulc(w1, w2);
        const int dbase = t + 192 * p;
        rowA[PHY(dbase)]       = a0;
        rowA[PHY(dbase + 64)]  = cmulc(a1, w1);
        rowA[PHY(dbase + 128)] = cmulc(a2, w2);
        rowA[PHY(dbase + 192)] = cmulc(a3, w3);
    }
    bar_frame(fl);

    // ---- stage 4 (radix-4, trivial twiddles) + rfft unpack — A -> X in B ----
    {
        const int t1 = u;
        const int t2 = (u == 0) ? 128 : 256 - u;
        float2 z1[4], z2[4];
#pragma unroll
        for (int r = 0; r < 4; r++) {
            z1[r] = rowA[PHY(t1 + (r << 8))];
            z2[r] = rowA[PHY(t2 + (r << 8))];
        }
        fft4(z1[0], z1[1], z1[2], z1[3]);
        fft4(z2[0], z2[1], z2[2], z2[3]);

        if (u == 0) {
            rowB[0]    = make_float2(z1[0].x + z1[0].y, 0.0f);
            rowB[1024] = make_float2(z1[0].x - z1[0].y, 0.0f);
            rowB[512]  = make_float2(z1[2].x, -z1[2].y);
            float2 Xk, Xc;
            unpack_pair(z1[1], z1[3], C4, C4, Xk, Xc);
            rowB[256] = Xk; rowB[768] = Xc;
            unpack_pair(z2[0], z2[3], 0.92387953f, 0.38268343f, Xk, Xc);
            rowB[128] = Xk; rowB[896] = Xc;
            unpack_pair(z2[1], z2[2], 0.38268343f, 0.92387953f, Xk, Xc);
            rowB[384] = Xk; rowB[640] = Xc;
        } else {
            float cb, sb;
            __sincosf((float)u * (PI_F / 1024.0f), &sb, &cb);
            const float cp = C4 * (cb - sb);
            const float sp = C4 * (cb + sb);
            float2 Xk, Xc;
            unpack_pair(z1[0], z2[3], cb, sb, Xk, Xc);
            rowB[u] = Xk; rowB[1024 - u] = Xc;
            unpack_pair(z1[1], z2[2], cp, sp, Xk, Xc);
            rowB[u + 256] = Xk; rowB[768 - u] = Xc;
            unpack_pair(z1[2], z2[1], -sb, cb, Xk, Xc);
            rowB[u + 512] = Xk; rowB[512 - u] = Xc;
            unpack_pair(z1[3], z2[0], -sp, cp, Xk, Xc);
            rowB[u + 768] = Xk; rowB[256 - u] = Xc;
        }
    }
    __syncthreads();

    // ---- transposed store: lane j -> frame j&3, bin j>>2 (+128/iter) ----
    // store-read banks: 8*fl + 2*k' (SROW=1028 => frame offset 8 banks):
    // 4 frames x 4 k per 16-lane phase -> all 16 distinct. Output runs 16B.
    const int  fs     = tid & 3;
    const int  kb     = tid >> 2;         // 0..127
    const int  fstore = g * FPB + fs;
    const bool valid  = (fstore < NFRAMES);
    const long ro       = ((long)b * NBINS) * NFRAMES + fstore;
    const long imag_off = (long)NB * NBINS * NFRAMES;
    const float2* __restrict__ Xrow = smem + (FPB + fs) * SROW;
#pragma unroll
    for (int i = 0; i < 9; i++) {
        const int k = kb + (i << 7);
        if (k <= NC && valid) {
            const float2 X = Xrow[k];
            const long o = ro + (long)k * NFRAMES;
            out[o]            = X.x;
            out[imag_off + o] = X.y;
        }
    }
}

extern "C" void kernel_launch(void* const* d_in, const int* in_sizes, int n_in,
                              void* d_out, int out_size) {
    const float* x   = (const float*)d_in[0];
    const float* win = (const float*)d_in[1];
    float* out = (float*)d_out;
    const int smem_bytes = 2 * FPB * SROW * (int)sizeof(float2);   // 65,792
    cudaFuncSetAttribute(stft_kernel, cudaFuncAttributeMaxDynamicSharedMemorySize,
                         smem_bytes);
    stft_kernel<<<NB * NGRP, THREADS, smem_bytes>>>(x, win, out);
}

// round 12
// speedup vs baseline: 1.1302x; 1.0878x over previous
#include <cuda_runtime.h>
#include <cuda_bf16.h>

// STFT: B=16, T=262144, n_fft=2048, hop=512, center reflect pad 1024.
// n_frames = 513, n_bins = 1025. Output [real(16,1025,513); imag(...)] fp32.
//
// 8 frames/CTA (512 thr, 64 thr/frame). 1024-pt complex FFT (real packing),
// Stockham radices 8,16,8. S1 reads gmem. S3 (radix-8, p=0) is self-owned
// in-place and fused with the rfft unpack (conjugate partners via 64-bit
// warp shuffles, columns c<->64-c on lanes l^16). X written once (self-owned,
// swizzled); full-sector (32B) transposed store. 6 smem passes, 4 sincosf.

#define NC        1024
#define SROW      1026
#define HOP       512
#define PADC      1024
#define T_LEN     262144
#define NFFT      2048
#define NFRAMES   513
#define NBINS     1025
#define NB        16
#define THREADS   512
#define FPB       8
#define NGRP      65
#define PI_F      3.14159265358979323846f
#define C4        0.70710678118654752f
#define C16       0.92387953251129f     // cos(pi/8)
#define S16       0.38268343236509f     // sin(pi/8)
#define CP16      0.98078528040323f     // cos(pi/16)
#define SP16      0.19509032201613f     // sin(pi/16)

// swizzle: XOR bits[3:6] and bit7 into low bits (bank-conflict-free patterns)
#define PHY(i) ((i) ^ ((((unsigned)(i)) >> 3) & 15u) ^ ((((((unsigned)(i)) >> 7) & 1u)) << 3))

__device__ __forceinline__ float2 cadd(float2 a, float2 b) { return make_float2(a.x + b.x, a.y + b.y); }
__device__ __forceinline__ float2 csub(float2 a, float2 b) { return make_float2(a.x - b.x, a.y - b.y); }
__device__ __forceinline__ float2 cmulc(float2 a, float2 w) {
    return make_float2(a.x * w.x - a.y * w.y, a.x * w.y + a.y * w.x);
}
// a * (c - i*s)
__device__ __forceinline__ float2 cmK(float2 a, float c, float s) {
    return make_float2(a.x * c + a.y * s, a.y * c - a.x * s);
}

__device__ __forceinline__ void fft8(float2* a) {
    float2 e0 = cadd(a[0], a[4]), e1 = cadd(a[1], a[5]);
    float2 e2 = cadd(a[2], a[6]), e3 = cadd(a[3], a[7]);
    float2 o0 = csub(a[0], a[4]), o1 = csub(a[1], a[5]);
    float2 o2 = csub(a[2], a[6]), o3 = csub(a[3], a[7]);
    float2 ee0 = cadd(e0, e2), ee1 = cadd(e1, e3);
    float2 eo0 = csub(e0, e2), eo1 = csub(e1, e3);
    a[0] = cadd(ee0, ee1);
    a[4] = csub(ee0, ee1);
    a[2] = make_float2(eo0.x + eo1.y, eo0.y - eo1.x);
    a[6] = make_float2(eo0.x - eo1.y, eo0.y + eo1.x);
    float2 p1 = make_float2(C4 * (o1.x + o1.y), C4 * (o1.y - o1.x));
    float2 p2 = make_float2(o2.y, -o2.x);
    float2 p3 = make_float2(C4 * (o3.y - o3.x), -C4 * (o3.x + o3.y));
    float2 s0 = cadd(o0, p2), s1 = cadd(p1, p3);
    float2 d0 = csub(o0, p2), d1 = csub(p1, p3);
    a[1] = cadd(s0, s1);
    a[5] = csub(s0, s1);
    a[3] = make_float2(d0.x + d1.y, d0.y - d1.x);
    a[7] = make_float2(d0.x - d1.y, d0.y + d1.x);
}

// natural-order 16-pt DFT: DIT from two fft8 (even/odd) + constant W16 combine
__device__ __forceinline__ void fft16n(float2* a) {
    float2 E[8], O[8];
#pragma unroll
    for (int j = 0; j < 8; j++) { E[j] = a[2 * j]; O[j] = a[2 * j + 1]; }
    fft8(E);
    fft8(O);
    float2 t;
    t = O[0];                       a[0] = cadd(E[0], t); a[8]  = csub(E[0], t);
    t = cmK(O[1],  C16,  S16);      a[1] = cadd(E[1], t); a[9]  = csub(E[1], t);
    t = cmK(O[2],  C4,   C4);       a[2] = cadd(E[2], t); a[10] = csub(E[2], t);
    t = cmK(O[3],  S16,  C16);      a[3] = cadd(E[3], t); a[11] = csub(E[3], t);
    t = make_float2(O[4].y, -O[4].x); a[4] = cadd(E[4], t); a[12] = csub(E[4], t);
    t = cmK(O[5], -S16,  C16);      a[5] = cadd(E[5], t); a[13] = csub(E[5], t);
    t = cmK(O[6], -C4,   C4);       a[6] = cadd(E[6], t); a[14] = csub(E[6], t);
    t = cmK(O[7], -C16,  S16);      a[7] = cadd(E[7], t); a[15] = csub(E[7], t);
}

// apply w^r to a[1..7] (serial chain)
__device__ __forceinline__ void twiddle8(float2* a, float2 w1) {
    float2 wk = w1;
    a[1] = cmulc(a[1], wk);
#pragma unroll
    for (int r = 2; r < 8; r++) { wk = cmulc(wk, w1); a[r] = cmulc(a[r], wk); }
}

__device__ __forceinline__ void bar_frame(int fl) {
    asm volatile("bar.sync %0, 64;" :: "r"(fl + 1) : "memory");
}

__device__ __forceinline__ float2 shfl16_f2(float2 v) {
    unsigned long long p = (unsigned long long)__float_as_uint(v.x) |
                           ((unsigned long long)__float_as_uint(v.y) << 32);
    p = __shfl_xor_sync(0xffffffffu, p, 16);
    return make_float2(__uint_as_float((unsigned)(p & 0xffffffffu)),
                       __uint_as_float((unsigned)(p >> 32)));
}

// X[k] from zk=Z[k], zn=Z[1024-k], (cw,sw)=(cos,sin)(pi*k/1024)
__device__ __forceinline__ float2 unpack_one(float2 zk, float2 zn, float cw, float sw) {
    const float er  = 0.5f * (zk.x + zn.x);
    const float ei  = 0.5f * (zk.y - zn.y);
    const float orr = 0.5f * (zk.y + zn.y);
    const float oi  = 0.5f * (zn.x - zk.x);
    return make_float2(er + (orr * cw + oi * sw), ei - (orr * sw - oi * cw));
}

extern __shared__ float2 buf[];   // FPB * SROW float2 = 65,664 B

__global__ __launch_bounds__(THREADS, 2)
void stft_kernel(const float* __restrict__ x,
                 const float* __restrict__ win,
                 float* __restrict__ out) {
    const int g   = blockIdx.x % NGRP;
    const int b   = blockIdx.x / NGRP;
    const int tid = threadIdx.x;
    const int fl  = tid >> 6;
    const int u   = tid & 63;
    const int f   = g * FPB + fl;
    const float* __restrict__ xb = x + (long)b * T_LEN;
    const int base = f * HOP - PADC;
    float2* __restrict__ row = buf + fl * SROW;

    // ---- stage 1: radix-8 (n=1024, s=1), gmem -> smem; butterflies u, u+64 ----
    const bool interior = (base >= 0) && (base + NFFT <= T_LEN);
#pragma unroll
    for (int h = 0; h < 2; h++) {
        const int t = u + (h << 6);
        float s1, c1;
        __sincosf((float)t * (-2.0f * PI_F / 1024.0f), &s1, &c1);
        float2 a[8];
        if (interior) {
            const float2* __restrict__ xv = (const float2*)(xb + base);
            const float2* __restrict__ wv = (const float2*)win;
#pragma unroll
            for (int r = 0; r < 8; r++) {
                const int n = t + (r << 7);
                const float2 v = xv[n];
                const float2 w = wv[n];
                a[r] = make_float2(v.x * w.x, v.y * w.y);
            }
        } else {
#pragma unroll
            for (int r = 0; r < 8; r++) {
                const int n = t + (r << 7);
                int t0 = base + 2 * n;
                int t1 = base + 2 * n + 1;
                t0 = (t0 < 0) ? -t0 : ((t0 >= T_LEN) ? 2 * T_LEN - 2 - t0 : t0);
                t1 = (t1 < 0) ? -t1 : ((t1 >= T_LEN) ? 2 * T_LEN - 2 - t1 : t1);
                a[r] = make_float2(xb[t0] * win[2 * n], xb[t1] * win[2 * n + 1]);
            }
        }
        fft8(a);
        twiddle8(a, make_float2(c1, s1));
#pragma unroll
        for (int r = 0; r < 8; r++) row[PHY(8 * t + r)] = a[r];
    }
    bar_frame(fl);

    // ---- stage 2: radix-16 (n=128, s=8), one butterfly/thread, in-place ----
    {
        const int q = u & 7;
        const int p = u >> 3;
        float s1, c1;
        __sincosf((float)p * (-2.0f * PI_F / 128.0f), &s1, &c1);
        float2 a[16];
#pragma unroll
        for (int r = 0; r < 16; r++) a[r] = row[PHY(u + (r << 6))];
        bar_frame(fl);                 // all frame reads done before writes
        fft16n(a);
        const float2 w1 = make_float2(c1, s1);
        const int dbase = q + (p << 7);
        row[PHY(dbase)] = a[0];
        float2 wk = w1;
        row[PHY(dbase + 8)] = cmulc(a[1], wk);
#pragma unroll
        for (int m = 2; m < 16; m++) {
            wk = cmulc(wk, w1);
            row[PHY(dbase + 8 * m)] = cmulc(a[m], wk);
        }
    }
    bar_frame(fl);

    // ---- stage 3: radix-8 (n=8, s=128, p=0) self-owned + rfft unpack ----
    // column map: conjugate columns (c, 64-c) live on lanes l ^ 16.
    const int l   = u & 31;
    const int w16 = (u >> 5) << 4;        // 0 or 16
    int c;
    if (l < 15)       c = l + 1 + w16;    // w0: 1..15   w1: 17..31
    else if (l == 15) c = w16;            // w0: 0       w1: 16
    else if (l < 31)  c = 79 - l - w16;   // w0: 63..49  w1: 47..33
    else              c = 32 + w16;       // w0: 32      w1: 48

    float ca, sa;
    __sincosf((float)c * (PI_F / 1024.0f), &sa, &ca);

    float2 A[8], B[8];
#pragma unroll
    for (int r = 0; r < 8; r++) {
        A[r] = row[PHY(c + (r << 7))];          // column c
        B[r] = row[PHY(c + 64 + (r << 7))];     // column c+64
    }
    fft8(A);    // A[r] = Z[c + 128r]
    fft8(B);    // B[r] = Z[c+64 + 128r]

    {
        // theta for B bins: + pi/16
        const float cb = ca * CP16 - sa * SP16;
        const float sb = sa * CP16 + ca * SP16;
        const float CT8[8] = { 1.0f,  C16,  C4,  S16, 0.0f, -S16, -C4, -C16 };
        const float ST8[8] = { 0.0f,  S16,  C4,  C16, 1.0f,  C16,  C4,  S16 };
        const bool cz = (c == 0), c32 = (c == 32);
#pragma unroll
        for (int r = 0; r < 8; r++) {
            // partner values (uniform shuffles, then per-thread select)
            float2 shB = shfl16_f2(B[7 - r]);   // partner's B[7-r]
            float2 shA = shfl16_f2(A[7 - r]);   // partner's A[7-r]
            float2 znA = c32 ? B[7 - r] : shB;
            float2 znB = c32 ? A[7 - r] : shA;
            if (cz) { znA = A[(8 - r) & 7]; znB = B[7 - r]; }

            // bin k = c + 128r
            if (cz && r == 0) {
                row[PHY(0)]    = make_float2(A[0].x + A[0].y, 0.0f);
                row[PHY(1024)] = make_float2(A[0].x - A[0].y, 0.0f);
            } else {
                const float cw = ca * CT8[r] - sa * ST8[r];
                const float sw = sa * CT8[r] + ca * ST8[r];
                row[PHY(c + (r << 7))] = unpack_one(A[r], znA, cw, sw);
            }
            // bin k = c + 64 + 128r
            {
                const float cw = cb * CT8[r] - sb * ST8[r];
                const float sw = sb * CT8[r] + cb * ST8[r];
                row[PHY(c + 64 + (r << 7))] = unpack_one(B[r], znB, cw, sw);
            }
        }
    }
    __syncthreads();

    // ---- transposed store: lane j -> frame j&7, bin j>>3 (+64/iter) ----
    const int  fs     = tid & 7;
    const int  kb     = tid >> 3;
    const int  fstore = g * FPB + fs;
    const bool valid  = (fstore < NFRAMES);
    const long ro       = ((long)b * NBINS) * NFRAMES + fstore;
    const long imag_off = (long)NB * NBINS * NFRAMES;
    const float2* __restrict__ Xrow = buf + fs * SROW;
#pragma unroll
    for (int i = 0; i < 17; i++) {
        const int k = kb + (i << 6);
        if (k <= NC && valid) {
            const float2 X = Xrow[PHY(k)];
            const long o = ro + (long)k * NFRAMES;
            out[o]            = X.x;
            out[imag_off + o] = X.y;
        }
    }
}

extern "C" void kernel_launch(void* const* d_in, const int* in_sizes, int n_in,
                              void* d_out, int out_size) {
    const float* x   = (const float*)d_in[0];
    const float* win = (const float*)d_in[1];
    float* out = (float*)d_out;
    const int smem_bytes = FPB * SROW * (int)sizeof(float2);   // 65,664
    cudaFuncSetAttribute(stft_kernel, cudaFuncAttributeMaxDynamicSharedMemorySize,
                         smem_bytes);
    stft_kernel<<<NB * NGRP, THREADS, smem_bytes>>>(x, win, out);
}

// round 13
// speedup vs baseline: 1.1470x; 1.0148x over previous
#include <cuda_runtime.h>
#include <cuda_bf16.h>

// STFT: B=16, T=262144, n_fft=2048, hop=512, center reflect pad 1024.
// n_frames = 513, n_bins = 1025. Output [real(16,1025,513); imag(...)] fp32.
//
// 8 frames/CTA (512 thr, 64 thr/frame). 1024-pt complex FFT (real packing),
// IN-PLACE Cooley-Tukey DIF, radices 8,8,4,(4): self-owned butterflies
// (read set == write set) -> one butterfly live at a time -> <=42 regs ->
// 3 CTAs/SM. Final radix-4 stage + digit-reversal + rfft unpack fused into
// the store phase (DFT4 on quads in registers). 3 barriers, 4 sincosf.

#define NC        1024
#define SROW      1027      // mod 16 == 3: frame bank offsets disjoint in store
#define HOP       512
#define PADC      1024
#define T_LEN     262144
#define NFFT      2048
#define NFRAMES   513
#define NBINS     1025
#define NB        16
#define THREADS   512
#define FPB       8
#define NGRP      65
#define PI_F      3.14159265358979323846f
#define C4        0.70710678118654752f
#define C16       0.92387953251129f     // cos(pi/8)
#define S16       0.38268343236509f     // sin(pi/8)

#define PHY(i) ((i) ^ ((((unsigned)(i)) >> 3) & 15u) ^ ((((((unsigned)(i)) >> 7) & 1u)) << 3))

__device__ __forceinline__ float2 cadd(float2 a, float2 b) { return make_float2(a.x + b.x, a.y + b.y); }
__device__ __forceinline__ float2 csub(float2 a, float2 b) { return make_float2(a.x - b.x, a.y - b.y); }
__device__ __forceinline__ float2 cmulc(float2 a, float2 w) {
    return make_float2(a.x * w.x - a.y * w.y, a.x * w.y + a.y * w.x);
}

__device__ __forceinline__ void fft8(float2* a) {
    float2 e0 = cadd(a[0], a[4]), e1 = cadd(a[1], a[5]);
    float2 e2 = cadd(a[2], a[6]), e3 = cadd(a[3], a[7]);
    float2 o0 = csub(a[0], a[4]), o1 = csub(a[1], a[5]);
    float2 o2 = csub(a[2], a[6]), o3 = csub(a[3], a[7]);
    float2 ee0 = cadd(e0, e2), ee1 = cadd(e1, e3);
    float2 eo0 = csub(e0, e2), eo1 = csub(e1, e3);
    a[0] = cadd(ee0, ee1);
    a[4] = csub(ee0, ee1);
    a[2] = make_float2(eo0.x + eo1.y, eo0.y - eo1.x);
    a[6] = make_float2(eo0.x - eo1.y, eo0.y + eo1.x);
    float2 p1 = make_float2(C4 * (o1.x + o1.y), C4 * (o1.y - o1.x));
    float2 p2 = make_float2(o2.y, -o2.x);
    float2 p3 = make_float2(C4 * (o3.y - o3.x), -C4 * (o3.x + o3.y));
    float2 s0 = cadd(o0, p2), s1 = cadd(p1, p3);
    float2 d0 = csub(o0, p2), d1 = csub(p1, p3);
    a[1] = cadd(s0, s1);
    a[5] = csub(s0, s1);
    a[3] = make_float2(d0.x + d1.y, d0.y - d1.x);
    a[7] = make_float2(d0.x - d1.y, d0.y + d1.x);
}

__device__ __forceinline__ void fft4(float2& a0, float2& a1, float2& a2, float2& a3) {
    float2 t0 = cadd(a0, a2), t1 = csub(a0, a2);
    float2 t2 = cadd(a1, a3), t3 = csub(a1, a3);
    a0 = cadd(t0, t2);
    a2 = csub(t0, t2);
    float2 b1 = make_float2(t1.x + t3.y, t1.y - t3.x);
    float2 b3 = make_float2(t1.x - t3.y, t1.y + t3.x);
    a1 = b1;
    a3 = b3;
}

__device__ __forceinline__ void twiddle8(float2* a, float2 w1) {
    float2 wk = w1;
    a[1] = cmulc(a[1], wk);
#pragma unroll
    for (int r = 2; r < 8; r++) { wk = cmulc(wk, w1); a[r] = cmulc(a[r], wk); }
}

__device__ __forceinline__ void bar_frame(int fl) {
    asm volatile("bar.sync %0, 64;" :: "r"(fl + 1) : "memory");
}

// X[k] from zk=Z[k], zn=Z[(1024-k)%1024], (cw,sw)=(cos,sin)(pi*k/1024)
__device__ __forceinline__ float2 unpack_one(float2 zk, float2 zn, float cw, float sw) {
    const float er  = 0.5f * (zk.x + zn.x);
    const float ei  = 0.5f * (zk.y - zn.y);
    const float orr = 0.5f * (zk.y + zn.y);
    const float oi  = 0.5f * (zn.x - zk.x);
    return make_float2(er + (orr * cw + oi * sw), ei - (orr * sw - oi * cw));
}

extern __shared__ float2 buf[];   // FPB * SROW float2 = 65,728 B

__global__ __launch_bounds__(THREADS, 3)
void stft_kernel(const float* __restrict__ x,
                 const float* __restrict__ win,
                 float* __restrict__ out) {
    const int g   = blockIdx.x % NGRP;
    const int b   = blockIdx.x / NGRP;
    const int tid = threadIdx.x;
    const int fl  = tid >> 6;
    const int u   = tid & 63;
    const int f   = g * FPB + fl;
    const float* __restrict__ xb = x + (long)b * T_LEN;
    const int base = f * HOP - PADC;
    float2* __restrict__ row = buf + fl * SROW;

    // ---- stage 1: in-place DIF radix-8 (n=1024): pos j+128m, j=u,u+64 ----
    const bool interior = (base >= 0) && (base + NFFT <= T_LEN);
#pragma unroll
    for (int h = 0; h < 2; h++) {
        const int j = u + (h << 6);
        float s1, c1;
        __sincosf((float)j * (-2.0f * PI_F / 1024.0f), &s1, &c1);
        float2 a[8];
        if (interior) {
            const float2* __restrict__ xv = (const float2*)(xb + base);
            const float2* __restrict__ wv = (const float2*)win;
#pragma unroll
            for (int m = 0; m < 8; m++) {
                const int n = j + (m << 7);
                const float2 v = xv[n];
                const float2 w = wv[n];
                a[m] = make_float2(v.x * w.x, v.y * w.y);
            }
        } else {
#pragma unroll
            for (int m = 0; m < 8; m++) {
                const int n = j + (m << 7);
                int t0 = base + 2 * n;
                int t1 = base + 2 * n + 1;
                t0 = (t0 < 0) ? -t0 : ((t0 >= T_LEN) ? 2 * T_LEN - 2 - t0 : t0);
                t1 = (t1 < 0) ? -t1 : ((t1 >= T_LEN) ? 2 * T_LEN - 2 - t1 : t1);
                a[m] = make_float2(xb[t0] * win[2 * n], xb[t1] * win[2 * n + 1]);
            }
        }
        fft8(a);
        twiddle8(a, make_float2(c1, s1));
#pragma unroll
        for (int m = 0; m < 8; m++) row[PHY(j + (m << 7))] = a[m];
    }
    bar_frame(fl);

    // ---- stage 2: in-place radix-8 on blocks of 128: pos 128b2+jj+16m ----
    {
        const int jj = u & 15;                 // same for both butterflies
        float s1, c1;
        __sincosf((float)jj * (-2.0f * PI_F / 128.0f), &s1, &c1);
        const float2 w1 = make_float2(c1, s1);
#pragma unroll
        for (int h = 0; h < 2; h++) {
            const int v  = u + (h << 6);
            const int bs = (v >> 4) << 7;      // 128 * block
            float2 a[8];
#pragma unroll
            for (int m = 0; m < 8; m++) a[m] = row[PHY(bs + jj + (m << 4))];
            fft8(a);
            twiddle8(a, w1);
#pragma unroll
            for (int m = 0; m < 8; m++) row[PHY(bs + jj + (m << 4))] = a[m];
        }
    }
    bar_frame(fl);

    // ---- stage 3: in-place radix-4 on blocks of 16: pos 16b3+jj+4m ----
    {
        const int jj = u & 3;                  // same for all 4 butterflies
        // wj = W16^jj = (cos, -sin)(jj*pi/8)
        const float wr = (jj == 0) ? 1.0f : (jj == 1) ? C16 : (jj == 2) ? C4 : S16;
        const float wi = (jj == 0) ? 0.0f : (jj == 1) ? -S16 : (jj == 2) ? -C4 : -C16;
        const float2 w1 = make_float2(wr, wi);
        const float2 w2 = cmulc(w1, w1);
        const float2 w3 = cmulc(w1, w2);
#pragma unroll
        for (int h = 0; h < 4; h++) {
            const int v  = u + (h << 6);
            const int bs = (v >> 2) << 4;      // 16 * block
            float2 a0 = row[PHY(bs + jj)];
            float2 a1 = row[PHY(bs + jj + 4)];
            float2 a2 = row[PHY(bs + jj + 8)];
            float2 a3 = row[PHY(bs + jj + 12)];
            fft4(a0, a1, a2, a3);
            row[PHY(bs + jj)]      = a0;
            row[PHY(bs + jj + 4)]  = cmulc(a1, w1);
            row[PHY(bs + jj + 8)]  = cmulc(a2, w2);
            row[PHY(bs + jj + 12)] = cmulc(a3, w3);
        }
    }
    __syncthreads();   // store phase reads other frames

    // ---- store phase: final radix-4 (blocks of 4) in registers + digit
    //      reversal + rfft unpack + transposed 32B-run stores.
    // Z[k] (natural order, k = d1 + 8d2 + 64d3 + 256d4) is element d4 of the
    // DFT4 of quad (d3 + 4d2 + 32d1). Conjugate of (kb,d3,d4):
    // kb>=1: (64-kb, 3-d3, 3-d4); kb==0: d3==0 -> same quad elem (4-d4)&3,
    //        d3>=1 -> quad 4-d3, elem 3-d4.
    {
        const int fs     = tid & 7;
        const int kb     = tid >> 3;           // 0..63
        const int fstore = g * FPB + fs;
        const bool valid = (fstore < NFRAMES);
        const long ro       = ((long)b * NBINS) * NFRAMES + fstore;
        const long imag_off = (long)NB * NBINS * NFRAMES;
        const float2* __restrict__ Zr = buf + fs * SROW;

        const int d1 = kb & 7, d2 = kb >> 3;
        const int kbc = (64 - kb) & 63;        // conjugate kb (kb>=1)
        const int d1c = kbc & 7, d2c = kbc >> 3;
        float ca, sa;
        __sincosf((float)kb * (PI_F / 1024.0f), &sa, &ca);

        // cos/sin(s*pi/16), s = d3 + 4*d4
        const float CT[16] = { 1.0f, 0.98078528f, 0.92387953f, 0.83146961f,
                               0.70710678f, 0.55557023f, 0.38268343f, 0.19509032f,
                               0.0f, -0.19509032f, -0.38268343f, -0.55557023f,
                              -0.70710678f, -0.83146961f, -0.92387953f, -0.98078528f };
        const float ST[16] = { 0.0f, 0.19509032f, 0.38268343f, 0.55557023f,
                               0.70710678f, 0.83146961f, 0.92387953f, 0.98078528f,
                               1.0f, 0.98078528f, 0.92387953f, 0.83146961f,
                               0.70710678f, 0.55557023f, 0.38268343f, 0.19509032f };

        float2 Z0sav = make_float2(0.0f, 0.0f);
#pragma unroll
        for (int d3 = 0; d3 < 4; d3++) {
            const bool selfq = (kb == 0) && (d3 == 0);
            const int qa = d3 + 4 * d2 + 32 * d1;
            float2 A[4];
#pragma unroll
            for (int e = 0; e < 4; e++) A[e] = Zr[PHY(4 * qa + e)];
            fft4(A[0], A[1], A[2], A[3]);
            if (selfq) Z0sav = A[0];

            float2 Bq[4];
            if (!selfq) {
                const int qb = (kb == 0) ? (4 - d3)
                                         : ((3 - d3) + 4 * d2c + 32 * d1c);
#pragma unroll
                for (int e = 0; e < 4; e++) Bq[e] = Zr[PHY(4 * qb + e)];
                fft4(Bq[0], Bq[1], Bq[2], Bq[3]);
            }

#pragma unroll
            for (int d4 = 0; d4 < 4; d4++) {
                const int s = d3 + 4 * d4;
                const float cw = ca * CT[s] - sa * ST[s];
                const float sw = sa * CT[s] + ca * ST[s];
                const float2 zk = A[d4];
                const float2 zn = selfq ? A[(4 - d4) & 3] : Bq[3 - d4];
                const float2 X = unpack_one(zk, zn, cw, sw);
                const int k = kb + 64 * s;
                if (valid) {
                    const long o = ro + (long)k * NFRAMES;
                    out[o]            = X.x;
                    out[imag_off + o] = X.y;
                }
            }
        }
        // Nyquist bin k=1024 (kb==0 threads): X = Z[0].re - Z[0].im
        if (kb == 0 && valid) {
            const long o = ro + (long)NC * NFRAMES;
            out[o]            = Z0sav.x - Z0sav.y;
            out[imag_off + o] = 0.0f;
        }
    }
}

extern "C" void kernel_launch(void* const* d_in, const int* in_sizes, int n_in,
                              void* d_out, int out_size) {
    const float* x   = (const float*)d_in[0];
    const float* win = (const float*)d_in[1];
    float* out = (float*)d_out;
    const int smem_bytes = FPB * SROW * (int)sizeof(float2);   // 65,728
    cudaFuncSetAttribute(stft_kernel, cudaFuncAttributeMaxDynamicSharedMemorySize,
                         smem_bytes);
    stft_kernel<<<NB * NGRP, THREADS, smem_bytes>>>(x, win, out);
}

// round 14
// speedup vs baseline: 1.3377x; 1.1662x over previous
#include <cuda_runtime.h>
#include <cuda_bf16.h>

// STFT: B=16, T=262144, n_fft=2048, hop=512, center reflect pad 1024.
// n_frames = 513, n_bins = 1025. Output [real(16,1025,513); imag(...)] fp32.
//
// 8 frames/CTA (512 thr, 64 thr/frame). 1024-pt complex FFT (real packing),
// in-place DIF radix-8 (stride 128) + radix-8 (blocks of 128) in smem, then
// the remaining 16-pt DFT per contiguous block of 16 is done IN REGISTERS in
// the store phase (per-thread), with rfft unpack using conjugate rows fetched
// via shfl.xor(16) (warp kb-map {2w,2w+1,64-2w,63-2w}). 4 smem passes,
// 2 barriers, 4 sincosf, direct 32B-run gmem stores.

#define NC        1024
#define SROW      1027
#define HOP       512
#define PADC      1024
#define T_LEN     262144
#define NFFT      2048
#define NFRAMES   513
#define NBINS     1025
#define NB        16
#define THREADS   512
#define FPB       8
#define NGRP      65
#define PI_F      3.14159265358979323846f
#define C4        0.70710678118654752f
#define C16       0.92387953251129f     // cos(pi/8)
#define S16       0.38268343236509f     // sin(pi/8)

#define PHY(i) ((i) ^ ((((unsigned)(i)) >> 3) & 15u) ^ ((((((unsigned)(i)) >> 7) & 1u)) << 3))

__device__ __forceinline__ float2 cadd(float2 a, float2 b) { return make_float2(a.x + b.x, a.y + b.y); }
__device__ __forceinline__ float2 csub(float2 a, float2 b) { return make_float2(a.x - b.x, a.y - b.y); }
__device__ __forceinline__ float2 cmulc(float2 a, float2 w) {
    return make_float2(a.x * w.x - a.y * w.y, a.x * w.y + a.y * w.x);
}
// a * (c - i*s)
__device__ __forceinline__ float2 cmK(float2 a, float c, float s) {
    return make_float2(a.x * c + a.y * s, a.y * c - a.x * s);
}

__device__ __forceinline__ void fft8(float2* a) {
    float2 e0 = cadd(a[0], a[4]), e1 = cadd(a[1], a[5]);
    float2 e2 = cadd(a[2], a[6]), e3 = cadd(a[3], a[7]);
    float2 o0 = csub(a[0], a[4]), o1 = csub(a[1], a[5]);
    float2 o2 = csub(a[2], a[6]), o3 = csub(a[3], a[7]);
    float2 ee0 = cadd(e0, e2), ee1 = cadd(e1, e3);
    float2 eo0 = csub(e0, e2), eo1 = csub(e1, e3);
    a[0] = cadd(ee0, ee1);
    a[4] = csub(ee0, ee1);
    a[2] = make_float2(eo0.x + eo1.y, eo0.y - eo1.x);
    a[6] = make_float2(eo0.x - eo1.y, eo0.y + eo1.x);
    float2 p1 = make_float2(C4 * (o1.x + o1.y), C4 * (o1.y - o1.x));
    float2 p2 = make_float2(o2.y, -o2.x);
    float2 p3 = make_float2(C4 * (o3.y - o3.x), -C4 * (o3.x + o3.y));
    float2 s0 = cadd(o0, p2), s1 = cadd(p1, p3);
    float2 d0 = csub(o0, p2), d1 = csub(p1, p3);
    a[1] = cadd(s0, s1);
    a[5] = csub(s0, s1);
    a[3] = make_float2(d0.x + d1.y, d0.y - d1.x);
    a[7] = make_float2(d0.x - d1.y, d0.y + d1.x);
}

__device__ __forceinline__ void fft4(float2& a0, float2& a1, float2& a2, float2& a3) {
    float2 t0 = cadd(a0, a2), t1 = csub(a0, a2);
    float2 t2 = cadd(a1, a3), t3 = csub(a1, a3);
    a0 = cadd(t0, t2);
    a2 = csub(t0, t2);
    float2 b1 = make_float2(t1.x + t3.y, t1.y - t3.x);
    float2 b3 = make_float2(t1.x - t3.y, t1.y + t3.x);
    a1 = b1;
    a3 = b3;
}

__device__ __forceinline__ void twiddle8(float2* a, float2 w1) {
    float2 wk = w1;
    a[1] = cmulc(a[1], wk);
#pragma unroll
    for (int r = 2; r < 8; r++) { wk = cmulc(wk, w1); a[r] = cmulc(a[r], wk); }
}

__device__ __forceinline__ void bar_frame(int fl) {
    asm volatile("bar.sync %0, 64;" :: "r"(fl + 1) : "memory");
}

__device__ __forceinline__ float2 shfl16_f2(float2 v) {
    unsigned long long p = (unsigned long long)__float_as_uint(v.x) |
                           ((unsigned long long)__float_as_uint(v.y) << 32);
    p = __shfl_xor_sync(0xffffffffu, p, 16);
    return make_float2(__uint_as_float((unsigned)(p & 0xffffffffu)),
                       __uint_as_float((unsigned)(p >> 32)));
}

// X[k] from zk=Z[k], zn=Z[(1024-k)%1024], (cw,sw)=(cos,sin)(pi*k/1024)
__device__ __forceinline__ float2 unpack_one(float2 zk, float2 zn, float cw, float sw) {
    const float er  = 0.5f * (zk.x + zn.x);
    const float ei  = 0.5f * (zk.y - zn.y);
    const float orr = 0.5f * (zk.y + zn.y);
    const float oi  = 0.5f * (zn.x - zk.x);
    return make_float2(er + (orr * cw + oi * sw), ei - (orr * sw - oi * cw));
}

extern __shared__ float2 buf[];   // FPB * SROW float2 = 65,728 B

__global__ __launch_bounds__(THREADS, 2)
void stft_kernel(const float* __restrict__ x,
                 const float* __restrict__ win,
                 float* __restrict__ out) {
    const int g   = blockIdx.x % NGRP;
    const int b   = blockIdx.x / NGRP;
    const int tid = threadIdx.x;
    const int fl  = tid >> 6;
    const int u   = tid & 63;
    const int f   = g * FPB + fl;
    const float* __restrict__ xb = x + (long)b * T_LEN;
    const int base = f * HOP - PADC;
    float2* __restrict__ row = buf + fl * SROW;

    // ---- stage 1: in-place DIF radix-8 (n=1024): pos j+128m, j=u,u+64 ----
    const bool interior = (base >= 0) && (base + NFFT <= T_LEN);
#pragma unroll
    for (int h = 0; h < 2; h++) {
        const int j = u + (h << 6);
        float s1, c1;
        __sincosf((float)j * (-2.0f * PI_F / 1024.0f), &s1, &c1);
        float2 a[8];
        if (interior) {
            const float2* __restrict__ xv = (const float2*)(xb + base);
            const float2* __restrict__ wv = (const float2*)win;
#pragma unroll
            for (int m = 0; m < 8; m++) {
                const int n = j + (m << 7);
                const float2 v = xv[n];
                const float2 w = wv[n];
                a[m] = make_float2(v.x * w.x, v.y * w.y);
            }
        } else {
#pragma unroll
            for (int m = 0; m < 8; m++) {
                const int n = j + (m << 7);
                int t0 = base + 2 * n;
                int t1 = base + 2 * n + 1;
                t0 = (t0 < 0) ? -t0 : ((t0 >= T_LEN) ? 2 * T_LEN - 2 - t0 : t0);
                t1 = (t1 < 0) ? -t1 : ((t1 >= T_LEN) ? 2 * T_LEN - 2 - t1 : t1);
                a[m] = make_float2(xb[t0] * win[2 * n], xb[t1] * win[2 * n + 1]);
            }
        }
        fft8(a);
        twiddle8(a, make_float2(c1, s1));
#pragma unroll
        for (int m = 0; m < 8; m++) row[PHY(j + (m << 7))] = a[m];
    }
    bar_frame(fl);

    // ---- stage 2: in-place radix-8 on blocks of 128: pos 128b2+jj+16m ----
    {
        const int jj = u & 15;
        float s1, c1;
        __sincosf((float)jj * (-2.0f * PI_F / 128.0f), &s1, &c1);
        const float2 w1 = make_float2(c1, s1);
#pragma unroll
        for (int h = 0; h < 2; h++) {
            const int v  = u + (h << 6);
            const int bs = (v >> 4) << 7;
            float2 a[8];
#pragma unroll
            for (int m = 0; m < 8; m++) a[m] = row[PHY(bs + jj + (m << 4))];
            fft8(a);
            twiddle8(a, w1);
#pragma unroll
            for (int m = 0; m < 8; m++) row[PHY(bs + jj + (m << 4))] = a[m];
        }
    }
    __syncthreads();   // store phase reads other frames

    // ---- store phase: 16-pt DFT per block of 16 in registers + unpack ----
    // thread -> (frame fs, row kb); warp kb-map puts conj rows on lane^16.
    {
        const int lane = tid & 31;
        const int w    = tid >> 5;          // warp 0..15
        const int fs   = lane & 7;
        const int c    = lane >> 3;         // 0..3
        int kb;
        if (w == 0) kb = (c == 0) ? 0 : (c == 1) ? 1 : (c == 2) ? 32 : 63;
        else {
            const int t2 = w << 1;
            kb = (c == 0) ? t2 : (c == 1) ? t2 + 1 : (c == 2) ? 64 - t2 : 63 - t2;
        }
        const int  fstore = g * FPB + fs;
        const bool valid  = (fstore < NFRAMES);
        const long ro       = ((long)b * NBINS) * NFRAMES + fstore;
        const long imag_off = (long)NB * NBINS * NFRAMES;
        const float2* __restrict__ Zr = buf + fs * SROW;

        const int bblk = (kb >> 3) + ((kb & 7) << 3);   // block of 16
        float2 a[16];
#pragma unroll
        for (int p = 0; p < 16; p++) a[p] = Zr[PHY((bblk << 4) + p)];

        // stage A: DFT4 over m (n = j + 4m), then *= W16^{j*k0}
#pragma unroll
        for (int j = 0; j < 4; j++) fft4(a[j], a[j + 4], a[j + 8], a[j + 12]);
        a[5]  = cmK(a[5],  C16, S16);    // j=1,k0=1: W16^1
        a[9]  = cmK(a[9],  C4,  C4);     // j=1,k0=2: W16^2
        a[13] = cmK(a[13], S16, C16);    // j=1,k0=3: W16^3
        a[6]  = cmK(a[6],  C4,  C4);     // j=2,k0=1: W16^2
        a[10] = make_float2(a[10].y, -a[10].x);   // j=2,k0=2: W16^4 = -i
        a[14] = cmK(a[14], -C4, C4);     // j=2,k0=3: W16^6
        a[7]  = cmK(a[7],  S16, C16);    // j=3,k0=1: W16^3
        a[11] = cmK(a[11], -C4, C4);     // j=3,k0=2: W16^6
        a[15] = cmK(a[15], -C16, -S16);  // j=3,k0=3: W16^9
        // stage B: DFT4 over j -> slot 4k0+k1 = Z[kb + 64(k0+4k1)]
#pragma unroll
        for (int k0 = 0; k0 < 4; k0++)
            fft4(a[4 * k0], a[4 * k0 + 1], a[4 * k0 + 2], a[4 * k0 + 3]);

        float ca, sa;
        __sincosf((float)kb * (PI_F / 1024.0f), &sa, &ca);
        const bool self0  = (kb == 0);
        const bool self32 = (kb == 32);

        // cos/sin(s*pi/16)
        const float CT[16] = { 1.0f, 0.98078528f, 0.92387953f, 0.83146961f,
                               0.70710678f, 0.55557023f, 0.38268343f, 0.19509032f,
                               0.0f, -0.19509032f, -0.38268343f, -0.55557023f,
                              -0.70710678f, -0.83146961f, -0.92387953f, -0.98078528f };
        const float ST[16] = { 0.0f, 0.19509032f, 0.38268343f, 0.55557023f,
                               0.70710678f, 0.83146961f, 0.92387953f, 0.98078528f,
                               1.0f, 0.98078528f, 0.92387953f, 0.83146961f,
                               0.70710678f, 0.55557023f, 0.38268343f, 0.19509032f };

#pragma unroll
        for (int k1 = 0; k1 < 4; k1++) {
#pragma unroll
            for (int k0 = 0; k0 < 4; k0++) {
                const int s     = k0 + 4 * k1;
                const int slot  = 4 * k0 + k1;
                const int cslot = 4 * (3 - k0) + (3 - k1);
                // partner's Z[1024-k] (shuffle executed by all lanes)
                const float2 sh = shfl16_f2(a[cslot]);
                float2 zn = self32 ? a[cslot] : sh;
                if (self0) {
                    const int sc = (16 - s) & 15;        // s=0 unused below
                    zn = a[4 * (sc & 3) + (sc >> 2)];
                }
                const int k = kb + 64 * s;
                if (self0 && s == 0) {
                    if (valid) {
                        out[ro]            = a[0].x + a[0].y;       // X[0]
                        out[imag_off + ro] = 0.0f;
                        const long oN = ro + (long)NC * NFRAMES;    // X[1024]
                        out[oN]            = a[0].x - a[0].y;
                        out[imag_off + oN] = 0.0f;
                    }
                } else {
                    const float cw = ca * CT[s] - sa * ST[s];
                    const float sw = sa * CT[s] + ca * ST[s];
                    const float2 X = unpack_one(a[slot], zn, cw, sw);
                    if (valid) {
                        const long o = ro + (long)k * NFRAMES;
                        out[o]            = X.x;
                        out[imag_off + o] = X.y;
                    }
                }
            }
        }
    }
}

extern "C" void kernel_launch(void* const* d_in, const int* in_sizes, int n_in,
                              void* d_out, int out_size) {
    const float* x   = (const float*)d_in[0];
    const float* win = (const float*)d_in[1];
    float* out = (float*)d_out;
    const int smem_bytes = FPB * SROW * (int)sizeof(float2);   // 65,728
    cudaFuncSetAttribute(stft_kernel, cudaFuncAttributeMaxDynamicSharedMemorySize,
                         smem_bytes);
    stft_kernel<<<NB * NGRP, THREADS, smem_bytes>>>(x, win, out);
}

// round 15
// speedup vs baseline: 1.4480x; 1.0825x over previous
#include <cuda_runtime.h>
#include <cuda_bf16.h>

// STFT: B=16, T=262144, n_fft=2048, hop=512, center reflect pad 1024.
// n_frames = 513, n_bins = 1025. Output [real(16,1025,513); imag(...)] fp32.
//
// 8 frames/CTA (512 thr, 64 thr/frame). 1024-pt complex FFT (real packing),
// in-place DIF radix-8 (stride 128) + radix-8 (blocks of 128) in smem
// (IDENTITY layout — patterns are naturally conflict-free), then the
// remaining 16-pt DFT per block of 16 in registers in the store phase,
// rfft unpack via float shfl.xor(16) pairs. 4 smem passes, 2 barriers,
// 3 sincosf, direct 32B-run gmem stores.

#define NC        1024
#define SROW      1027
#define HOP       512
#define PADC      1024
#define T_LEN     262144
#define NFFT      2048
#define NFRAMES   513
#define NBINS     1025
#define NB        16
#define THREADS   512
#define FPB       8
#define NGRP      65
#define PI_F      3.14159265358979323846f
#define C4        0.70710678118654752f
#define C16       0.92387953251129f     // cos(pi/8)
#define S16       0.38268343236509f     // sin(pi/8)

__device__ __forceinline__ float2 cadd(float2 a, float2 b) { return make_float2(a.x + b.x, a.y + b.y); }
__device__ __forceinline__ float2 csub(float2 a, float2 b) { return make_float2(a.x - b.x, a.y - b.y); }
__device__ __forceinline__ float2 cmulc(float2 a, float2 w) {
    return make_float2(a.x * w.x - a.y * w.y, a.x * w.y + a.y * w.x);
}
// a * (c - i*s)
__device__ __forceinline__ float2 cmK(float2 a, float c, float s) {
    return make_float2(a.x * c + a.y * s, a.y * c - a.x * s);
}

__device__ __forceinline__ void fft8(float2* a) {
    float2 e0 = cadd(a[0], a[4]), e1 = cadd(a[1], a[5]);
    float2 e2 = cadd(a[2], a[6]), e3 = cadd(a[3], a[7]);
    float2 o0 = csub(a[0], a[4]), o1 = csub(a[1], a[5]);
    float2 o2 = csub(a[2], a[6]), o3 = csub(a[3], a[7]);
    float2 ee0 = cadd(e0, e2), ee1 = cadd(e1, e3);
    float2 eo0 = csub(e0, e2), eo1 = csub(e1, e3);
    a[0] = cadd(ee0, ee1);
    a[4] = csub(ee0, ee1);
    a[2] = make_float2(eo0.x + eo1.y, eo0.y - eo1.x);
    a[6] = make_float2(eo0.x - eo1.y, eo0.y + eo1.x);
    float2 p1 = make_float2(C4 * (o1.x + o1.y), C4 * (o1.y - o1.x));
    float2 p2 = make_float2(o2.y, -o2.x);
    float2 p3 = make_float2(C4 * (o3.y - o3.x), -C4 * (o3.x + o3.y));
    float2 s0 = cadd(o0, p2), s1 = cadd(p1, p3);
    float2 d0 = csub(o0, p2), d1 = csub(p1, p3);
    a[1] = cadd(s0, s1);
    a[5] = csub(s0, s1);
    a[3] = make_float2(d0.x + d1.y, d0.y - d1.x);
    a[7] = make_float2(d0.x - d1.y, d0.y + d1.x);
}

__device__ __forceinline__ void fft4(float2& a0, float2& a1, float2& a2, float2& a3) {
    float2 t0 = cadd(a0, a2), t1 = csub(a0, a2);
    float2 t2 = cadd(a1, a3), t3 = csub(a1, a3);
    a0 = cadd(t0, t2);
    a2 = csub(t0, t2);
    float2 b1 = make_float2(t1.x + t3.y, t1.y - t3.x);
    float2 b3 = make_float2(t1.x - t3.y, t1.y + t3.x);
    a1 = b1;
    a3 = b3;
}

__device__ __forceinline__ void twiddle8(float2* a, float2 w1) {
    float2 wk = w1;
    a[1] = cmulc(a[1], wk);
#pragma unroll
    for (int r = 2; r < 8; r++) { wk = cmulc(wk, w1); a[r] = cmulc(a[r], wk); }
}

__device__ __forceinline__ void bar_frame(int fl) {
    asm volatile("bar.sync %0, 64;" :: "r"(fl + 1) : "memory");
}

__device__ __forceinline__ float2 shfl16_f2(float2 v) {
    return make_float2(__shfl_xor_sync(0xffffffffu, v.x, 16),
                       __shfl_xor_sync(0xffffffffu, v.y, 16));
}

// X[k] from zk=Z[k], zn=Z[(1024-k)%1024], (cw,sw)=(cos,sin)(pi*k/1024)
__device__ __forceinline__ float2 unpack_one(float2 zk, float2 zn, float cw, float sw) {
    const float er  = 0.5f * (zk.x + zn.x);
    const float ei  = 0.5f * (zk.y - zn.y);
    const float orr = 0.5f * (zk.y + zn.y);
    const float oi  = 0.5f * (zn.x - zk.x);
    return make_float2(er + (orr * cw + oi * sw), ei - (orr * sw - oi * cw));
}

extern __shared__ float2 buf[];   // FPB * SROW float2 = 65,728 B

__global__ __launch_bounds__(THREADS, 2)
void stft_kernel(const float* __restrict__ x,
                 const float* __restrict__ win,
                 float* __restrict__ out) {
    const int g   = blockIdx.x % NGRP;
    const int b   = blockIdx.x / NGRP;
    const int tid = threadIdx.x;
    const int fl  = tid >> 6;
    const int u   = tid & 63;
    const int f   = g * FPB + fl;
    const float* __restrict__ xb = x + (long)b * T_LEN;
    const int base = f * HOP - PADC;
    float2* __restrict__ row = buf + fl * SROW;

    // ---- stage 1: in-place DIF radix-8 (n=1024): pos j+128m, j=u,u+64 ----
    // One sincosf; second root = w * exp(-i*pi/8).
    const bool interior = (base >= 0) && (base + NFFT <= T_LEN);
    float2 Wroot;
    {
        float s1, c1;
        __sincosf((float)u * (-2.0f * PI_F / 1024.0f), &s1, &c1);
        Wroot = make_float2(c1, s1);
    }
#pragma unroll
    for (int h = 0; h < 2; h++) {
        const int j = u + (h << 6);
        const float2 w1 = (h == 0) ? Wroot : cmK(Wroot, C16, S16);
        float2 a[8];
        if (interior) {
            const float2* __restrict__ xv = (const float2*)(xb + base);
            const float2* __restrict__ wv = (const float2*)win;
#pragma unroll
            for (int m = 0; m < 8; m++) {
                const int n = j + (m << 7);
                const float2 v = xv[n];
                const float2 w = wv[n];
                a[m] = make_float2(v.x * w.x, v.y * w.y);
            }
        } else {
#pragma unroll
            for (int m = 0; m < 8; m++) {
                const int n = j + (m << 7);
                int t0 = base + 2 * n;
                int t1 = base + 2 * n + 1;
                t0 = (t0 < 0) ? -t0 : ((t0 >= T_LEN) ? 2 * T_LEN - 2 - t0 : t0);
                t1 = (t1 < 0) ? -t1 : ((t1 >= T_LEN) ? 2 * T_LEN - 2 - t1 : t1);
                a[m] = make_float2(xb[t0] * win[2 * n], xb[t1] * win[2 * n + 1]);
            }
        }
        fft8(a);
        twiddle8(a, w1);
#pragma unroll
        for (int m = 0; m < 8; m++) row[j + (m << 7)] = a[m];
    }
    bar_frame(fl);

    // ---- stage 2: in-place radix-8 on blocks of 128: pos 128b2+jj+16m ----
    {
        const int jj = u & 15;
        float s1, c1;
        __sincosf((float)jj * (-2.0f * PI_F / 128.0f), &s1, &c1);
        const float2 w1 = make_float2(c1, s1);
#pragma unroll
        for (int h = 0; h < 2; h++) {
            const int v  = u + (h << 6);
            const int bs = (v >> 4) << 7;
            float2 a[8];
#pragma unroll
            for (int m = 0; m < 8; m++) a[m] = row[bs + jj + (m << 4)];
            fft8(a);
            twiddle8(a, w1);
#pragma unroll
            for (int m = 0; m < 8; m++) row[bs + jj + (m << 4)] = a[m];
        }
    }
    __syncthreads();   // store phase reads other frames

    // ---- store phase: 16-pt DFT per block of 16 in registers + unpack ----
    {
        const int lane = tid & 31;
        const int w    = tid >> 5;          // warp 0..15
        const int fs   = lane & 7;
        const int c    = lane >> 3;         // 0..3
        int kb;
        if (w == 0) kb = (c == 0) ? 0 : (c == 1) ? 1 : (c == 2) ? 32 : 63;
        else {
            const int t2 = w << 1;
            kb = (c == 0) ? t2 : (c == 1) ? t2 + 1 : (c == 2) ? 64 - t2 : 63 - t2;
        }
        const int  fstore = g * FPB + fs;
        const bool valid  = (fstore < NFRAMES);
        const long ro       = ((long)b * NBINS) * NFRAMES + fstore;
        const long imag_off = (long)NB * NBINS * NFRAMES;
        const float2* __restrict__ Zr = buf + fs * SROW;

        const int bblk = (kb >> 3) + ((kb & 7) << 3);   // block of 16
        float2 a[16];
#pragma unroll
        for (int p = 0; p < 16; p++) a[p] = Zr[(bblk << 4) + p];

        // stage A: DFT4 over m (n = j + 4m), then *= W16^{j*k0}
#pragma unroll
        for (int j = 0; j < 4; j++) fft4(a[j], a[j + 4], a[j + 8], a[j + 12]);
        a[5]  = cmK(a[5],  C16, S16);
        a[9]  = cmK(a[9],  C4,  C4);
        a[13] = cmK(a[13], S16, C16);
        a[6]  = cmK(a[6],  C4,  C4);
        a[10] = make_float2(a[10].y, -a[10].x);
        a[14] = cmK(a[14], -C4, C4);
        a[7]  = cmK(a[7],  S16, C16);
        a[11] = cmK(a[11], -C4, C4);
        a[15] = cmK(a[15], -C16, -S16);
        // stage B: DFT4 over j -> slot 4k0+k1 = Z[kb + 64(k0+4k1)]
#pragma unroll
        for (int k0 = 0; k0 < 4; k0++)
            fft4(a[4 * k0], a[4 * k0 + 1], a[4 * k0 + 2], a[4 * k0 + 3]);

        float ca, sa;
        __sincosf((float)kb * (PI_F / 1024.0f), &sa, &ca);
        const bool self0  = (kb == 0);
        const bool self32 = (kb == 32);

        const float CT[16] = { 1.0f, 0.98078528f, 0.92387953f, 0.83146961f,
                               0.70710678f, 0.55557023f, 0.38268343f, 0.19509032f,
                               0.0f, -0.19509032f, -0.38268343f, -0.55557023f,
                              -0.70710678f, -0.83146961f, -0.92387953f, -0.98078528f };
        const float ST[16] = { 0.0f, 0.19509032f, 0.38268343f, 0.55557023f,
                               0.70710678f, 0.83146961f, 0.92387953f, 0.98078528f,
                               1.0f, 0.98078528f, 0.92387953f, 0.83146961f,
                               0.70710678f, 0.55557023f, 0.38268343f, 0.19509032f };

#pragma unroll
        for (int k1 = 0; k1 < 4; k1++) {
#pragma unroll
            for (int k0 = 0; k0 < 4; k0++) {
                const int s     = k0 + 4 * k1;
                const int slot  = 4 * k0 + k1;
                const int cslot = 4 * (3 - k0) + (3 - k1);
                const float2 sh = shfl16_f2(a[cslot]);
                float2 zn = self32 ? a[cslot] : sh;
                if (self0) {
                    const int sc = (16 - s) & 15;
                    zn = a[4 * (sc & 3) + (sc >> 2)];
                }
                const int k = kb + 64 * s;
                if (self0 && s == 0) {
                    if (valid) {
                        out[ro]            = a[0].x + a[0].y;       // X[0]
                        out[imag_off + ro] = 0.0f;
                        const long oN = ro + (long)NC * NFRAMES;    // X[1024]
                        out[oN]            = a[0].x - a[0].y;
                        out[imag_off + oN] = 0.0f;
                    }
                } else {
                    const float cw = ca * CT[s] - sa * ST[s];
                    const float sw = sa * CT[s] + ca * ST[s];
                    const float2 X = unpack_one(a[slot], zn, cw, sw);
                    if (valid) {
                        const long o = ro + (long)k * NFRAMES;
                        out[o]            = X.x;
                        out[imag_off + o] = X.y;
                    }
                }
            }
        }
    }
}

extern "C" void kernel_launch(void* const* d_in, const int* in_sizes, int n_in,
                              void* d_out, int out_size) {
    const float* x   = (const float*)d_in[0];
    const float* win = (const float*)d_in[1];
    float* out = (float*)d_out;
    const int smem_bytes = FPB * SROW * (int)sizeof(float2);   // 65,728
    cudaFuncSetAttribute(stft_kernel, cudaFuncAttributeMaxDynamicSharedMemorySize,
                         smem_bytes);
    stft_kernel<<<NB * NGRP, THREADS, smem_bytes>>>(x, win, out);
}

// round 16
// speedup vs baseline: 1.4856x; 1.0260x over previous
#include <cuda_runtime.h>
#include <cuda_bf16.h>

// STFT: B=16, T=262144, n_fft=2048, hop=512, center reflect pad 1024.
// n_frames = 513, n_bins = 1025. Output [real(16,1025,513); imag(...)] fp32.
//
// 8 frames/CTA (512 thr, 64 thr/frame). 1024-pt complex FFT (real packing),
// in-place DIF radix-8 (stride 128, butterflies PAIRED j=2u,2u+1 for 128-bit
// gmem/smem traffic) + radix-8 (blocks of 128) in smem (identity layout),
// then 16-pt DFT per block of 16 in registers in the store phase (float4
// smem loads, SROW=1026 tiles banks), rfft unpack via shfl.xor(16).
// 4 smem passes, 2 barriers, 3 sincosf, 32B-run gmem stores.

#define NC        1024
#define SROW      1026      // == 2 (mod 16): float4 phases tile all banks
#define HOP       512
#define PADC      1024
#define T_LEN     262144
#define NFFT      2048
#define NFRAMES   513
#define NBINS     1025
#define NB        16
#define THREADS   512
#define FPB       8
#define NGRP      65
#define PI_F      3.14159265358979323846f
#define C4        0.70710678118654752f
#define C16       0.92387953251129f     // cos(pi/8)
#define S16       0.38268343236509f     // sin(pi/8)
#define C1K       0.99998117528260f     // cos(2*pi/1024)
#define S1K       0.00613588464915f     // sin(2*pi/1024)

__device__ __forceinline__ float2 cadd(float2 a, float2 b) { return make_float2(a.x + b.x, a.y + b.y); }
__device__ __forceinline__ float2 csub(float2 a, float2 b) { return make_float2(a.x - b.x, a.y - b.y); }
__device__ __forceinline__ float2 cmulc(float2 a, float2 w) {
    return make_float2(a.x * w.x - a.y * w.y, a.x * w.y + a.y * w.x);
}
// a * (c - i*s)
__device__ __forceinline__ float2 cmK(float2 a, float c, float s) {
    return make_float2(a.x * c + a.y * s, a.y * c - a.x * s);
}

__device__ __forceinline__ void fft8(float2* a) {
    float2 e0 = cadd(a[0], a[4]), e1 = cadd(a[1], a[5]);
    float2 e2 = cadd(a[2], a[6]), e3 = cadd(a[3], a[7]);
    float2 o0 = csub(a[0], a[4]), o1 = csub(a[1], a[5]);
    float2 o2 = csub(a[2], a[6]), o3 = csub(a[3], a[7]);
    float2 ee0 = cadd(e0, e2), ee1 = cadd(e1, e3);
    float2 eo0 = csub(e0, e2), eo1 = csub(e1, e3);
    a[0] = cadd(ee0, ee1);
    a[4] = csub(ee0, ee1);
    a[2] = make_float2(eo0.x + eo1.y, eo0.y - eo1.x);
    a[6] = make_float2(eo0.x - eo1.y, eo0.y + eo1.x);
    float2 p1 = make_float2(C4 * (o1.x + o1.y), C4 * (o1.y - o1.x));
    float2 p2 = make_float2(o2.y, -o2.x);
    float2 p3 = make_float2(C4 * (o3.y - o3.x), -C4 * (o3.x + o3.y));
    float2 s0 = cadd(o0, p2), s1 = cadd(p1, p3);
    float2 d0 = csub(o0, p2), d1 = csub(p1, p3);
    a[1] = cadd(s0, s1);
    a[5] = csub(s0, s1);
    a[3] = make_float2(d0.x + d1.y, d0.y - d1.x);
    a[7] = make_float2(d0.x - d1.y, d0.y + d1.x);
}

__device__ __forceinline__ void fft4(float2& a0, float2& a1, float2& a2, float2& a3) {
    float2 t0 = cadd(a0, a2), t1 = csub(a0, a2);
    float2 t2 = cadd(a1, a3), t3 = csub(a1, a3);
    a0 = cadd(t0, t2);
    a2 = csub(t0, t2);
    float2 b1 = make_float2(t1.x + t3.y, t1.y - t3.x);
    float2 b3 = make_float2(t1.x - t3.y, t1.y + t3.x);
    a1 = b1;
    a3 = b3;
}

__device__ __forceinline__ void twiddle8(float2* a, float2 w1) {
    float2 wk = w1;
    a[1] = cmulc(a[1], wk);
#pragma unroll
    for (int r = 2; r < 8; r++) { wk = cmulc(wk, w1); a[r] = cmulc(a[r], wk); }
}

__device__ __forceinline__ void bar_frame(int fl) {
    asm volatile("bar.sync %0, 64;" :: "r"(fl + 1) : "memory");
}

__device__ __forceinline__ float2 shfl16_f2(float2 v) {
    return make_float2(__shfl_xor_sync(0xffffffffu, v.x, 16),
                       __shfl_xor_sync(0xffffffffu, v.y, 16));
}

// X[k] from zk=Z[k], zn=Z[(1024-k)%1024], (cw,sw)=(cos,sin)(pi*k/1024)
__device__ __forceinline__ float2 unpack_one(float2 zk, float2 zn, float cw, float sw) {
    const float er  = 0.5f * (zk.x + zn.x);
    const float ei  = 0.5f * (zk.y - zn.y);
    const float orr = 0.5f * (zk.y + zn.y);
    const float oi  = 0.5f * (zn.x - zk.x);
    return make_float2(er + (orr * cw + oi * sw), ei - (orr * sw - oi * cw));
}

extern __shared__ float2 buf[];   // FPB * SROW float2 = 65,664 B

__global__ __launch_bounds__(THREADS, 2)
void stft_kernel(const float* __restrict__ x,
                 const float* __restrict__ win,
                 float* __restrict__ out) {
    const int g   = blockIdx.x % NGRP;
    const int b   = blockIdx.x / NGRP;
    const int tid = threadIdx.x;
    const int fl  = tid >> 6;
    const int u   = tid & 63;
    const int f   = g * FPB + fl;
    const float* __restrict__ xb = x + (long)b * T_LEN;
    const int base = f * HOP - PADC;
    float2* __restrict__ row = buf + fl * SROW;

    // ---- stage 1: in-place DIF radix-8 (n=1024), paired butterflies
    //      j = 2u, 2u+1 -> all gmem/smem traffic 128-bit ----
    const bool interior = (base >= 0) && (base + NFFT <= T_LEN);
    {
        float2 A[2][8];
        if (interior) {
            const float4* __restrict__ xv4 = (const float4*)(xb + base);
            const float4* __restrict__ wv4 = (const float4*)win;
#pragma unroll
            for (int m = 0; m < 8; m++) {
                const float4 v = xv4[u + (m << 6)];
                const float4 w = wv4[u + (m << 6)];
                A[0][m] = make_float2(v.x * w.x, v.y * w.y);
                A[1][m] = make_float2(v.z * w.z, v.w * w.w);
            }
        } else {
#pragma unroll
            for (int m = 0; m < 8; m++) {
                const int e0 = base + 4 * u + 256 * m;   // element of x (pre-window)
#pragma unroll
                for (int q = 0; q < 2; q++) {
                    int t0 = e0 + 2 * q;
                    int t1 = e0 + 2 * q + 1;
                    t0 = (t0 < 0) ? -t0 : ((t0 >= T_LEN) ? 2 * T_LEN - 2 - t0 : t0);
                    t1 = (t1 < 0) ? -t1 : ((t1 >= T_LEN) ? 2 * T_LEN - 2 - t1 : t1);
                    const int wbase = 4 * u + 256 * m + 2 * q;
                    A[q][m] = make_float2(xb[t0] * win[wbase],
                                          xb[t1] * win[wbase + 1]);
                }
            }
        }
        float2 Wa;
        {
            float s1, c1;
            __sincosf((float)(2 * u) * (-2.0f * PI_F / 1024.0f), &s1, &c1);
            Wa = make_float2(c1, s1);
        }
        const float2 Wb = cmK(Wa, C1K, S1K);
        fft8(A[0]);
        twiddle8(A[0], Wa);
        fft8(A[1]);
        twiddle8(A[1], Wb);
        float4* __restrict__ r4 = (float4*)row;
#pragma unroll
        for (int m = 0; m < 8; m++)
            r4[u + (m << 6)] = make_float4(A[0][m].x, A[0][m].y,
                                           A[1][m].x, A[1][m].y);
    }
    bar_frame(fl);

    // ---- stage 2: in-place radix-8 on blocks of 128: pos 128b2+jj+16m ----
    {
        const int jj = u & 15;
        float s1, c1;
        __sincosf((float)jj * (-2.0f * PI_F / 128.0f), &s1, &c1);
        const float2 w1 = make_float2(c1, s1);
#pragma unroll
        for (int h = 0; h < 2; h++) {
            const int v  = u + (h << 6);
            const int bs = (v >> 4) << 7;
            float2 a[8];
#pragma unroll
            for (int m = 0; m < 8; m++) a[m] = row[bs + jj + (m << 4)];
            fft8(a);
            twiddle8(a, w1);
#pragma unroll
            for (int m = 0; m < 8; m++) row[bs + jj + (m << 4)] = a[m];
        }
    }
    __syncthreads();   // store phase reads other frames

    // ---- store phase: 16-pt DFT per block of 16 in registers + unpack ----
    {
        const int lane = tid & 31;
        const int w    = tid >> 5;          // warp 0..15
        const int fs   = lane & 7;
        const int c    = lane >> 3;         // 0..3
        int kb;
        if (w == 0) kb = (c == 0) ? 0 : (c == 1) ? 1 : (c == 2) ? 32 : 63;
        else {
            const int t2 = w << 1;
            kb = (c == 0) ? t2 : (c == 1) ? t2 + 1 : (c == 2) ? 64 - t2 : 63 - t2;
        }
        const int  fstore = g * FPB + fs;
        const bool valid  = (fstore < NFRAMES);
        const long ro       = ((long)b * NBINS) * NFRAMES + fstore;
        const long imag_off = (long)NB * NBINS * NFRAMES;
        const float4* __restrict__ Zr4 = (const float4*)(buf + fs * SROW);

        const int bblk = (kb >> 3) + ((kb & 7) << 3);   // block of 16
        float2 a[16];
#pragma unroll
        for (int p = 0; p < 8; p++) {
            const float4 v = Zr4[(bblk << 3) + p];
            a[2 * p]     = make_float2(v.x, v.y);
            a[2 * p + 1] = make_float2(v.z, v.w);
        }

        // stage A: DFT4 over m (n = j + 4m), then *= W16^{j*k0}
#pragma unroll
        for (int j = 0; j < 4; j++) fft4(a[j], a[j + 4], a[j + 8], a[j + 12]);
        a[5]  = cmK(a[5],  C16, S16);
        a[9]  = cmK(a[9],  C4,  C4);
        a[13] = cmK(a[13], S16, C16);
        a[6]  = cmK(a[6],  C4,  C4);
        a[10] = make_float2(a[10].y, -a[10].x);
        a[14] = cmK(a[14], -C4, C4);
        a[7]  = cmK(a[7],  S16, C16);
        a[11] = cmK(a[11], -C4, C4);
        a[15] = cmK(a[15], -C16, -S16);
        // stage B: DFT4 over j -> slot 4k0+k1 = Z[kb + 64(k0+4k1)]
#pragma unroll
        for (int k0 = 0; k0 < 4; k0++)
            fft4(a[4 * k0], a[4 * k0 + 1], a[4 * k0 + 2], a[4 * k0 + 3]);

        float ca, sa;
        __sincosf((float)kb * (PI_F / 1024.0f), &sa, &ca);
        const bool self0  = (kb == 0);
        const bool self32 = (kb == 32);

        const float CT[16] = { 1.0f, 0.98078528f, 0.92387953f, 0.83146961f,
                               0.70710678f, 0.55557023f, 0.38268343f, 0.19509032f,
                               0.0f, -0.19509032f, -0.38268343f, -0.55557023f,
                              -0.70710678f, -0.83146961f, -0.92387953f, -0.98078528f };
        const float ST[16] = { 0.0f, 0.19509032f, 0.38268343f, 0.55557023f,
                               0.70710678f, 0.83146961f, 0.92387953f, 0.98078528f,
                               1.0f, 0.98078528f, 0.92387953f, 0.83146961f,
                               0.70710678f, 0.55557023f, 0.38268343f, 0.19509032f };

#pragma unroll
        for (int k1 = 0; k1 < 4; k1++) {
#pragma unroll
            for (int k0 = 0; k0 < 4; k0++) {
                const int s     = k0 + 4 * k1;
                const int slot  = 4 * k0 + k1;
                const int cslot = 4 * (3 - k0) + (3 - k1);
                const float2 sh = shfl16_f2(a[cslot]);
                float2 zn = self32 ? a[cslot] : sh;
                if (self0) {
                    const int sc = (16 - s) & 15;
                    zn = a[4 * (sc & 3) + (sc >> 2)];
                }
                const int k = kb + 64 * s;
                if (self0 && s == 0) {
                    if (valid) {
                        out[ro]            = a[0].x + a[0].y;       // X[0]
                        out[imag_off + ro] = 0.0f;
                        const long oN = ro + (long)NC * NFRAMES;    // X[1024]
                        out[oN]            = a[0].x - a[0].y;
                        out[imag_off + oN] = 0.0f;
                    }
                } else {
                    const float cw = ca * CT[s] - sa * ST[s];
                    const float sw = sa * CT[s] + ca * ST[s];
                    const float2 X = unpack_one(a[slot], zn, cw, sw);
                    if (valid) {
                        const long o = ro + (long)k * NFRAMES;
                        out[o]            = X.x;
                        out[imag_off + o] = X.y;
                    }
                }
            }
        }
    }
}

extern "C" void kernel_launch(void* const* d_in, const int* in_sizes, int n_in,
                              void* d_out, int out_size) {
    const float* x   = (const float*)d_in[0];
    const float* win = (const float*)d_in[1];
    float* out = (float*)d_out;
    const int smem_bytes = FPB * SROW * (int)sizeof(float2);   // 65,664
    cudaFuncSetAttribute(stft_kernel, cudaFuncAttributeMaxDynamicSharedMemorySize,
                         smem_bytes);
    stft_kernel<<<NB * NGRP, THREADS, smem_bytes>>>(x, win, out);
}